// round 1
// baseline (speedup 1.0000x reference)
#include <cuda_runtime.h>

#define NN 100000
#define EE 1600000
#define HIDC 128
#define GG 100
#define BN_EPS 1e-5f

typedef unsigned long long ull;

// ------------------------- scratch (device globals) -------------------------
__device__ int    g_cnt[NN];
__device__ int    g_offs[NN + 1];
__device__ int    g_cursor[NN];
__device__ float2 g_sattr[EE];
__device__ float  g_M1[NN * HIDC];
__device__ float  g_M2[NN * HIDC];
__device__ float  g_R1[NN * HIDC];
__device__ float  g_R2[NN * HIDC];
__device__ float  g_sum1[HIDC], g_sq1[HIDC], g_sum2[HIDC], g_sq2[HIDC];
__device__ float  g_mu1[HIDC], g_inv1[HIDC], g_mu2[HIDC], g_inv2[HIDC];
__device__ float  g_gmax1[GG * HIDC], g_gsum1[GG * HIDC];
__device__ float  g_gmax2[GG * HIDC], g_gsum2[GG * HIDC];
__device__ int    g_gcnt[GG];

// ------------------------- f32x2 helpers (sm_100+) -------------------------
__device__ __forceinline__ ull pack2(float lo, float hi) {
    ull r;
    asm("mov.b64 %0, {%1, %2};" : "=l"(r) : "f"(lo), "f"(hi));
    return r;
}
__device__ __forceinline__ void unpack2(ull v, float& lo, float& hi) {
    asm("mov.b64 {%0, %1}, %2;" : "=f"(lo), "=f"(hi) : "l"(v));
}
__device__ __forceinline__ void ffma2(ull& d, ull a, ull b) {
    asm("fma.rn.f32x2 %0, %1, %2, %0;" : "+l"(d) : "l"(a), "l"(b));
}

// ------------------------- K0: zero scratch -------------------------
__global__ void zero_kernel() {
    int i = blockIdx.x * blockDim.x + threadIdx.x;
    int stride = gridDim.x * blockDim.x;
    for (int j = i; j < NN; j += stride) g_cnt[j] = 0;
    for (int j = i; j < GG * HIDC; j += stride) {
        g_gmax1[j] = 0.f; g_gsum1[j] = 0.f;
        g_gmax2[j] = 0.f; g_gsum2[j] = 0.f;
    }
    if (i < HIDC) { g_sum1[i] = 0.f; g_sq1[i] = 0.f; g_sum2[i] = 0.f; g_sq2[i] = 0.f; }
    if (i < GG) g_gcnt[i] = 0;
}

// ------------------------- K1: histograms -------------------------
__global__ void hist_kernel(const int* __restrict__ ei, const int* __restrict__ batch) {
    int stride = gridDim.x * blockDim.x;
    int t0 = blockIdx.x * blockDim.x + threadIdx.x;
    for (int e = t0; e < EE; e += stride)
        atomicAdd(&g_cnt[ei[EE + e]], 1);
    for (int n = t0; n < NN; n += stride)
        atomicAdd(&g_gcnt[batch[n]], 1);
}

// ------------------------- K2: exclusive scan (single block) -------------------------
__global__ void scan_kernel() {
    __shared__ int sh[1024];
    __shared__ int carry;
    int tid = threadIdx.x;
    if (tid == 0) carry = 0;
    __syncthreads();
    for (int base = 0; base < NN; base += 1024) {
        int i = base + tid;
        int v = (i < NN) ? g_cnt[i] : 0;
        sh[tid] = v;
        __syncthreads();
        for (int off = 1; off < 1024; off <<= 1) {
            int t = (tid >= off) ? sh[tid - off] : 0;
            __syncthreads();
            sh[tid] += t;
            __syncthreads();
        }
        int incl = sh[tid];
        int excl = incl - v;
        int cbase = carry;
        if (i < NN) {
            g_offs[i] = cbase + excl;
            g_cursor[i] = cbase + excl;
        }
        __syncthreads();
        if (tid == 1023) carry = cbase + incl;
        __syncthreads();
    }
    if (tid == 0) g_offs[NN] = EE;
}

// ------------------------- K3: scatter edge attrs by target -------------------------
__global__ void scatter_kernel(const int* __restrict__ ei, const float2* __restrict__ ea) {
    int stride = gridDim.x * blockDim.x;
    for (int e = blockIdx.x * blockDim.x + threadIdx.x; e < EE; e += stride) {
        int t = ei[EE + e];
        int pos = atomicAdd(&g_cursor[t], 1);
        g_sattr[pos] = ea[e];
    }
}

// ------------------------- K4: per-node aggregation of t = relu(ea@W1^T + b1) ----
__global__ void __launch_bounds__(256) aggregate_kernel(
    const float* __restrict__ c1W1, const float* __restrict__ c1b1,
    const float* __restrict__ c2W1, const float* __restrict__ c2b1) {
    int gwarp = (blockIdx.x * blockDim.x + threadIdx.x) >> 5;
    int lane = threadIdx.x & 31;
    if (gwarp >= NN) return;
    int n = gwarp;
    int c0 = lane * 4;

    float w1x[4], w1y[4], b1r[4], w2x[4], w2y[4], b2r[4];
#pragma unroll
    for (int j = 0; j < 4; j++) {
        w1x[j] = c1W1[(c0 + j) * 2 + 0];
        w1y[j] = c1W1[(c0 + j) * 2 + 1];
        b1r[j] = c1b1[c0 + j];
        w2x[j] = c2W1[(c0 + j) * 2 + 0];
        w2y[j] = c2W1[(c0 + j) * 2 + 1];
        b2r[j] = c2b1[c0 + j];
    }
    int s = g_offs[n], e = g_offs[n + 1];
    float a1[4] = {0.f, 0.f, 0.f, 0.f};
    float a2[4] = {0.f, 0.f, 0.f, 0.f};
    for (int i = s; i < e; i++) {
        float2 at = g_sattr[i];
#pragma unroll
        for (int j = 0; j < 4; j++) {
            float t1 = fmaf(at.y, w1y[j], fmaf(at.x, w1x[j], b1r[j]));
            a1[j] += fmaxf(t1, 0.f);
            float t2 = fmaf(at.y, w2y[j], fmaf(at.x, w2x[j], b2r[j]));
            a2[j] += fmaxf(t2, 0.f);
        }
    }
    float invc = (e > s) ? 1.f / (float)(e - s) : 0.f;
    *(float4*)&g_M1[n * HIDC + c0] =
        make_float4(a1[0] * invc, a1[1] * invc, a1[2] * invc, a1[3] * invc);
    *(float4*)&g_M2[n * HIDC + c0] =
        make_float4(a2[0] * invc, a2[1] * invc, a2[2] * invc, a2[3] * invc);
}

// ------------------------- K5: R = relu(M @ W2^T + b2*[cnt>0]) -------------------------
#define AS_STRIDE 129
#define BS_STRIDE 132
#define GEMM_SMEM ((128 * AS_STRIDE + 128 * BS_STRIDE) * 4)

__global__ void __launch_bounds__(256) gemm_kernel(
    int which, const float* __restrict__ W2, const float* __restrict__ b2) {
    const float* Mmat = which ? g_M2 : g_M1;
    float* R = which ? g_R2 : g_R1;

    extern __shared__ float sh[];
    float* As = sh;                       // [128][129]
    float* Bs = sh + 128 * AS_STRIDE;     // [128][132], Bs[k][c] = W2[c][k]

    int tid = threadIdx.x;
    int rowBase = blockIdx.x * 128;

    for (int idx = tid; idx < 128 * 128; idx += 256) {
        int r = idx >> 7, k = idx & 127;
        int gr = rowBase + r;
        As[r * AS_STRIDE + k] = (gr < NN) ? Mmat[gr * HIDC + k] : 0.f;
    }
    for (int idx = tid; idx < 128 * 128; idx += 256) {
        int c = idx >> 7, k = idx & 127;
        Bs[k * BS_STRIDE + c] = W2[idx];
    }
    __syncthreads();

    int tx = tid & 15, ty = tid >> 4;
    ull acc[8][4];
#pragma unroll
    for (int i = 0; i < 8; i++)
#pragma unroll
        for (int j = 0; j < 4; j++) acc[i][j] = 0ULL;

    const float* AsBase = As + (ty * 8) * AS_STRIDE;
    const float* BsBase = Bs + tx * 8;

#pragma unroll 4
    for (int k = 0; k < 128; k++) {
        ull ap[8];
#pragma unroll
        for (int i = 0; i < 8; i++) {
            float a = AsBase[i * AS_STRIDE + k];
            ap[i] = pack2(a, a);
        }
        float4 bv0 = *(const float4*)(BsBase + k * BS_STRIDE);
        float4 bv1 = *(const float4*)(BsBase + k * BS_STRIDE + 4);
        ull bp[4] = {pack2(bv0.x, bv0.y), pack2(bv0.z, bv0.w),
                     pack2(bv1.x, bv1.y), pack2(bv1.z, bv1.w)};
#pragma unroll
        for (int i = 0; i < 8; i++)
#pragma unroll
            for (int j = 0; j < 4; j++) ffma2(acc[i][j], ap[i], bp[j]);
    }

    float bias[8];
#pragma unroll
    for (int j = 0; j < 8; j++) bias[j] = b2[tx * 8 + j];

#pragma unroll
    for (int i = 0; i < 8; i++) {
        int gr = rowBase + ty * 8 + i;
        if (gr < NN) {
            float bs = (g_cnt[gr] > 0) ? 1.f : 0.f;
            float o[8];
#pragma unroll
            for (int j = 0; j < 4; j++) {
                float lo, hi;
                unpack2(acc[i][j], lo, hi);
                o[2 * j]     = fmaxf(fmaf(bias[2 * j], bs, lo), 0.f);
                o[2 * j + 1] = fmaxf(fmaf(bias[2 * j + 1], bs, hi), 0.f);
            }
            float4* dst = (float4*)&R[gr * HIDC + tx * 8];
            dst[0] = make_float4(o[0], o[1], o[2], o[3]);
            dst[1] = make_float4(o[4], o[5], o[6], o[7]);
        }
    }
}

// ------------------------- K5b: BN stats (sum, sumsq per channel) -------------------------
__global__ void stats_kernel() {
    int c = threadIdx.x & 127;
    int which = threadIdx.x >> 7;
    const float* R = which ? g_R2 : g_R1;
    float s = 0.f, q = 0.f;
    for (int n = blockIdx.x; n < NN; n += gridDim.x) {
        float v = R[n * HIDC + c];
        s += v;
        q = fmaf(v, v, q);
    }
    if (which) {
        atomicAdd(&g_sum2[c], s);
        atomicAdd(&g_sq2[c], q);
    } else {
        atomicAdd(&g_sum1[c], s);
        atomicAdd(&g_sq1[c], q);
    }
}

// ------------------------- K5c: finalize BN stats -------------------------
__global__ void finalize_kernel() {
    int t = threadIdx.x;
    const float invN = 1.f / (float)NN;
    if (t < HIDC) {
        float mu = g_sum1[t] * invN;
        float var = fmaxf(g_sq1[t] * invN - mu * mu, 0.f);
        g_mu1[t] = mu;
        g_inv1[t] = rsqrtf(var + BN_EPS);
    } else {
        int c = t - HIDC;
        float mu = g_sum2[c] * invN;
        float var = fmaxf(g_sq2[c] * invN - mu * mu, 0.f);
        g_mu2[c] = mu;
        g_inv2[c] = rsqrtf(var + BN_EPS);
    }
}

// ------------------------- K6: BN+relu, node_pool out, graph max/sum pooling ----
__global__ void __launch_bounds__(256) combine_kernel(
    const int* __restrict__ batch,
    const float* __restrict__ bn1_b,
    const float* __restrict__ bn2_g, const float* __restrict__ bn2_b,
    const float* __restrict__ bn3_g, const float* __restrict__ bn3_b,
    float* __restrict__ out) {
    int c = threadIdx.x & 127;
    int half = threadIdx.x >> 7;
    float h0c = fmaxf(bn1_b[c], 0.f);
    float mu1 = g_mu1[c], iv1 = g_inv1[c], ga1 = bn2_g[c], be1 = bn2_b[c];
    float mu2 = g_mu2[c], iv2 = g_inv2[c], ga2 = bn3_g[c], be2 = bn3_b[c];

    int start = blockIdx.x * 256;
    int end = min(NN, start + 256);
    float mx1 = 0.f, sm1 = 0.f, mx2 = 0.f, sm2 = 0.f;
    int curg = -1;

    for (int n = start + half; n < end; n += 2) {
        int g = batch[n];
        if (g != curg) {
            if (curg >= 0) {
                atomicMax((int*)&g_gmax1[curg * HIDC + c], __float_as_int(mx1));
                atomicAdd(&g_gsum1[curg * HIDC + c], sm1);
                atomicMax((int*)&g_gmax2[curg * HIDC + c], __float_as_int(mx2));
                atomicAdd(&g_gsum2[curg * HIDC + c], sm2);
            }
            curg = g;
            mx1 = 0.f; sm1 = 0.f; mx2 = 0.f; sm2 = 0.f;
        }
        float r1 = g_R1[n * HIDC + c];
        float h1 = fmaxf(fmaf(ga1 * (r1 - mu1), iv1, be1), 0.f);
        float r2 = g_R2[n * HIDC + c];
        float h2 = fmaxf(fmaf(ga2 * (r2 - mu2), iv2, be2), 0.f);
        out[n * HIDC + c] = h0c + h1 + h2;
        mx1 = fmaxf(mx1, h1); sm1 += h1;
        mx2 = fmaxf(mx2, h2); sm2 += h2;
    }
    if (curg >= 0) {
        atomicMax((int*)&g_gmax1[curg * HIDC + c], __float_as_int(mx1));
        atomicAdd(&g_gsum1[curg * HIDC + c], sm1);
        atomicMax((int*)&g_gmax2[curg * HIDC + c], __float_as_int(mx2));
        atomicAdd(&g_gsum2[curg * HIDC + c], sm2);
    }
}

// ------------------------- K7: graph head -------------------------
__global__ void head_kernel(
    const float* __restrict__ bn1_b,
    const float* __restrict__ Wp0, const float* __restrict__ bp0,
    const float* __restrict__ Wp1, const float* __restrict__ bp1,
    const float* __restrict__ Wp2, const float* __restrict__ bp2,
    float* __restrict__ out) {
    int g = blockIdx.x, c = threadIdx.x;
    float invn = 1.f / fmaxf((float)g_gcnt[g], 1.f);
    float acc = bp0[c] + bp1[c] + bp2[c];
    const float* w0 = Wp0 + c * 256;
    const float* w1 = Wp1 + c * 256;
    const float* w2 = Wp2 + c * 256;
    for (int k = 0; k < HIDC; k++) {
        float h0k = fmaxf(bn1_b[k], 0.f);
        acc = fmaf(w0[k] + w0[128 + k], h0k, acc);
        acc = fmaf(w1[k], g_gmax1[g * HIDC + k], acc);
        acc = fmaf(w1[128 + k], g_gsum1[g * HIDC + k] * invn, acc);
        acc = fmaf(w2[k], g_gmax2[g * HIDC + k], acc);
        acc = fmaf(w2[128 + k], g_gsum2[g * HIDC + k] * invn, acc);
    }
    out[NN * HIDC + g * HIDC + c] = acc;
}

// ------------------------- launch -------------------------
extern "C" void kernel_launch(void* const* d_in, const int* in_sizes, int n_in,
                              void* d_out, int out_size) {
    const float* edge_attr = (const float*)d_in[1];
    const float* bn1_b = (const float*)d_in[5];
    const float* bn2_g = (const float*)d_in[6];
    const float* bn2_b = (const float*)d_in[7];
    const float* bn3_g = (const float*)d_in[8];
    const float* bn3_b = (const float*)d_in[9];
    const float* c1_W1 = (const float*)d_in[10];
    const float* c1_b1 = (const float*)d_in[11];
    const float* c1_W2 = (const float*)d_in[12];
    const float* c1_b2 = (const float*)d_in[13];
    const float* c2_W1 = (const float*)d_in[14];
    const float* c2_b1 = (const float*)d_in[15];
    const float* c2_W2 = (const float*)d_in[16];
    const float* c2_b2 = (const float*)d_in[17];
    const float* Wp0 = (const float*)d_in[18];
    const float* bp0 = (const float*)d_in[19];
    const float* Wp1 = (const float*)d_in[20];
    const float* bp1 = (const float*)d_in[21];
    const float* Wp2 = (const float*)d_in[22];
    const float* bp2 = (const float*)d_in[23];
    const int* edge_index = (const int*)d_in[24];
    const int* batch = (const int*)d_in[25];
    float* out = (float*)d_out;

    cudaFuncSetAttribute(gemm_kernel, cudaFuncAttributeMaxDynamicSharedMemorySize,
                         GEMM_SMEM);

    zero_kernel<<<256, 256>>>();
    hist_kernel<<<2048, 256>>>(edge_index, batch);
    scan_kernel<<<1, 1024>>>();
    scatter_kernel<<<2048, 256>>>(edge_index, (const float2*)edge_attr);
    aggregate_kernel<<<(NN + 7) / 8, 256>>>(c1_W1, c1_b1, c2_W1, c2_b1);
    gemm_kernel<<<(NN + 127) / 128, 256, GEMM_SMEM>>>(0, c1_W2, c1_b2);
    gemm_kernel<<<(NN + 127) / 128, 256, GEMM_SMEM>>>(1, c2_W2, c2_b2);
    stats_kernel<<<512, 256>>>();
    finalize_kernel<<<1, 256>>>();
    combine_kernel<<<(NN + 255) / 256, 256>>>(batch, bn1_b, bn2_g, bn2_b, bn3_g,
                                              bn3_b, out);
    head_kernel<<<GG, HIDC>>>(bn1_b, Wp0, bp0, Wp1, bp1, Wp2, bp2, out);
}

// round 2
// speedup vs baseline: 1.4018x; 1.4018x over previous
#include <cuda_runtime.h>

#define NN 100000
#define EE 1600000
#define HIDC 128
#define GG 100
#define BN_EPS 1e-5f
#define NBLK 98            // ceil(NN/1024)
#define AST 132            // smem row stride (floats), 16B-aligned

typedef unsigned long long ull;

// ------------------------- scratch (device globals) -------------------------
__device__ int    g_cnt[NN];
__device__ int    g_offs[NN + 1];
__device__ int    g_cursor[NN];
__device__ int    g_bsum[NBLK];
__device__ int    g_bbase[NBLK];
__device__ float2 g_sattr[EE];
__device__ float  g_R1[NN * HIDC];
__device__ float  g_R2[NN * HIDC];
__device__ float  g_sum1[HIDC], g_sq1[HIDC], g_sum2[HIDC], g_sq2[HIDC];
__device__ float  g_mu1[HIDC], g_inv1[HIDC], g_mu2[HIDC], g_inv2[HIDC];
__device__ float  g_gmax1[GG * HIDC], g_gsum1[GG * HIDC];
__device__ float  g_gmax2[GG * HIDC], g_gsum2[GG * HIDC];
__device__ int    g_gcnt[GG];

// ------------------------- f32x2 helpers (sm_100+) -------------------------
__device__ __forceinline__ ull pack2(float lo, float hi) {
    ull r;
    asm("mov.b64 %0, {%1, %2};" : "=l"(r) : "f"(lo), "f"(hi));
    return r;
}
__device__ __forceinline__ void unpack2(ull v, float& lo, float& hi) {
    asm("mov.b64 {%0, %1}, %2;" : "=f"(lo), "=f"(hi) : "l"(v));
}
__device__ __forceinline__ void ffma2(ull& d, ull a, ull b) {
    asm("fma.rn.f32x2 %0, %1, %2, %0;" : "+l"(d) : "l"(a), "l"(b));
}

// ------------------------- K0: zero scratch -------------------------
__global__ void zero_kernel() {
    int i = blockIdx.x * blockDim.x + threadIdx.x;
    int stride = gridDim.x * blockDim.x;
    for (int j = i; j < NN; j += stride) g_cnt[j] = 0;
    for (int j = i; j < GG * HIDC; j += stride) {
        g_gmax1[j] = 0.f; g_gsum1[j] = 0.f;
        g_gmax2[j] = 0.f; g_gsum2[j] = 0.f;
    }
    if (i < HIDC) { g_sum1[i] = 0.f; g_sq1[i] = 0.f; g_sum2[i] = 0.f; g_sq2[i] = 0.f; }
    if (i < GG) g_gcnt[i] = 0;
}

// ------------------------- K1: histograms -------------------------
__global__ void hist_kernel(const int* __restrict__ ei, const int* __restrict__ batch) {
    int stride = gridDim.x * blockDim.x;
    int t0 = blockIdx.x * blockDim.x + threadIdx.x;
    for (int e = t0; e < EE; e += stride)
        atomicAdd(&g_cnt[ei[EE + e]], 1);
    for (int n = t0; n < NN; n += stride)
        atomicAdd(&g_gcnt[batch[n]], 1);
}

// ------------------------- K2a: per-block exclusive scan -------------------------
__global__ void __launch_bounds__(1024) scanA_kernel() {
    __shared__ int sh[1024];
    int tid = threadIdx.x;
    int i = blockIdx.x * 1024 + tid;
    int v = (i < NN) ? g_cnt[i] : 0;
    sh[tid] = v;
    __syncthreads();
#pragma unroll
    for (int off = 1; off < 1024; off <<= 1) {
        int t = (tid >= off) ? sh[tid - off] : 0;
        __syncthreads();
        sh[tid] += t;
        __syncthreads();
    }
    int incl = sh[tid];
    if (i < NN) g_offs[i] = incl - v;   // exclusive within block (base added later)
    if (tid == 1023) g_bsum[blockIdx.x] = incl;
}

// ------------------------- K2b: scan the block totals (tiny) -------------------------
__global__ void scanB_kernel() {
    __shared__ int sh[128];
    int t = threadIdx.x;
    int v = (t < NBLK) ? g_bsum[t] : 0;
    sh[t] = v;
    __syncthreads();
#pragma unroll
    for (int off = 1; off < 128; off <<= 1) {
        int x = (t >= off) ? sh[t - off] : 0;
        __syncthreads();
        sh[t] += x;
        __syncthreads();
    }
    if (t < NBLK) g_bbase[t] = sh[t] - v;  // exclusive
}

// ------------------------- K2c: add block bases -------------------------
__global__ void __launch_bounds__(1024) scanC_kernel() {
    int i = blockIdx.x * 1024 + threadIdx.x;
    int base = g_bbase[blockIdx.x];
    if (i < NN) {
        int o = g_offs[i] + base;
        g_offs[i] = o;
        g_cursor[i] = o;
    }
    if (i == NN - 1) g_offs[NN] = EE;
}

// ------------------------- K3: scatter edge attrs by target -------------------------
__global__ void scatter_kernel(const int* __restrict__ ei, const float2* __restrict__ ea) {
    int stride = gridDim.x * blockDim.x;
    for (int e = blockIdx.x * blockDim.x + threadIdx.x; e < EE; e += stride) {
        int t = ei[EE + e];
        int pos = atomicAdd(&g_cursor[t], 1);
        g_sattr[pos] = ea[e];
    }
}

// ------------------------- K4: fused aggregate + 2x GEMM + BN stats -------------------------
// smem layout: As1[128][AST] | As2[128][AST] | Bs[128][AST]
#define FUSED_SMEM (3 * 128 * AST * 4)

__global__ void __launch_bounds__(512) fused_kernel(
    const float* __restrict__ c1W1, const float* __restrict__ c1b1,
    const float* __restrict__ c1W2, const float* __restrict__ c1b2,
    const float* __restrict__ c2W1, const float* __restrict__ c2b1,
    const float* __restrict__ c2W2, const float* __restrict__ c2b2) {
    extern __shared__ float sh[];
    float* As1 = sh;
    float* As2 = sh + 128 * AST;
    float* Bs  = sh + 2 * 128 * AST;

    int tid = threadIdx.x;
    int rowBase = blockIdx.x * 128;
    int w = tid >> 5, lane = tid & 31;
    int c0 = lane * 4;

    // ---- phase 1: aggregation of t = relu(ea@W1^T + b1), mean per node ----
    {
        float w1x[4], w1y[4], b1r[4], w2x[4], w2y[4], b2r[4];
#pragma unroll
        for (int j = 0; j < 4; j++) {
            w1x[j] = c1W1[(c0 + j) * 2 + 0];
            w1y[j] = c1W1[(c0 + j) * 2 + 1];
            b1r[j] = c1b1[c0 + j];
            w2x[j] = c2W1[(c0 + j) * 2 + 0];
            w2y[j] = c2W1[(c0 + j) * 2 + 1];
            b2r[j] = c2b1[c0 + j];
        }
        // 16 warps, 8 nodes each
        for (int i = 0; i < 8; i++) {
            int r = w * 8 + i;
            int gr = rowBase + r;
            float a1[4] = {0.f, 0.f, 0.f, 0.f};
            float a2[4] = {0.f, 0.f, 0.f, 0.f};
            if (gr < NN) {
                int s = g_offs[gr], e = g_offs[gr + 1];
                for (int k = s; k < e; k++) {
                    float2 at = g_sattr[k];
#pragma unroll
                    for (int j = 0; j < 4; j++) {
                        float t1 = fmaf(at.y, w1y[j], fmaf(at.x, w1x[j], b1r[j]));
                        a1[j] += fmaxf(t1, 0.f);
                        float t2 = fmaf(at.y, w2y[j], fmaf(at.x, w2x[j], b2r[j]));
                        a2[j] += fmaxf(t2, 0.f);
                    }
                }
                float invc = (e > s) ? 1.f / (float)(e - s) : 0.f;
#pragma unroll
                for (int j = 0; j < 4; j++) { a1[j] *= invc; a2[j] *= invc; }
            }
            *(float4*)&As1[r * AST + c0] = make_float4(a1[0], a1[1], a1[2], a1[3]);
            *(float4*)&As2[r * AST + c0] = make_float4(a2[0], a2[1], a2[2], a2[3]);
        }
    }

    // ---- phase 2: two GEMMs R = relu(As @ W2^T + b2*[cnt>0]) with fused stats ----
    int tx = tid & 15;     // 16 col-groups of 8
    int ty = tid >> 4;     // 32 row-groups of 4

    for (int which = 0; which < 2; which++) {
        const float* W2  = which ? c2W2 : c1W2;
        const float* b2v = which ? c2b2 : c1b2;
        const float* Asrc = which ? As2 : As1;
        float* R = which ? g_R2 : g_R1;

        __syncthreads();   // aggregation done / previous epilogue done
        // load Bs[k][c] = W2[c][k]
        for (int idx = tid; idx < 128 * 128; idx += 512) {
            int c = idx >> 7, k = idx & 127;
            Bs[k * AST + c] = W2[idx];
        }
        __syncthreads();

        ull acc[4][4];
#pragma unroll
        for (int i = 0; i < 4; i++)
#pragma unroll
            for (int j = 0; j < 4; j++) acc[i][j] = 0ULL;

        const float* AsBase = Asrc + (ty * 4) * AST;
        const float* BsBase = Bs + tx * 8;

#pragma unroll 4
        for (int k = 0; k < 128; k++) {
            ull ap[4];
#pragma unroll
            for (int i = 0; i < 4; i++) {
                float a = AsBase[i * AST + k];
                ap[i] = pack2(a, a);
            }
            float4 bv0 = *(const float4*)(BsBase + k * AST);
            float4 bv1 = *(const float4*)(BsBase + k * AST + 4);
            ull bp[4] = {pack2(bv0.x, bv0.y), pack2(bv0.z, bv0.w),
                         pack2(bv1.x, bv1.y), pack2(bv1.z, bv1.w)};
#pragma unroll
            for (int i = 0; i < 4; i++)
#pragma unroll
                for (int j = 0; j < 4; j++) ffma2(acc[i][j], ap[i], bp[j]);
        }
        __syncthreads();   // all As1 reads done -> As1 reusable as reduction scratch

        float bias[8];
#pragma unroll
        for (int j = 0; j < 8; j++) bias[j] = b2v[tx * 8 + j];

        float colsum[8] = {0.f,0.f,0.f,0.f,0.f,0.f,0.f,0.f};
        float colsq[8]  = {0.f,0.f,0.f,0.f,0.f,0.f,0.f,0.f};

#pragma unroll
        for (int i = 0; i < 4; i++) {
            int gr = rowBase + ty * 4 + i;
            if (gr < NN) {
                float bs = (g_cnt[gr] > 0) ? 1.f : 0.f;
                float o[8];
#pragma unroll
                for (int j = 0; j < 4; j++) {
                    float lo, hi;
                    unpack2(acc[i][j], lo, hi);
                    o[2 * j]     = fmaxf(fmaf(bias[2 * j], bs, lo), 0.f);
                    o[2 * j + 1] = fmaxf(fmaf(bias[2 * j + 1], bs, hi), 0.f);
                }
                float4* dst = (float4*)&R[gr * HIDC + tx * 8];
                dst[0] = make_float4(o[0], o[1], o[2], o[3]);
                dst[1] = make_float4(o[4], o[5], o[6], o[7]);
#pragma unroll
                for (int j = 0; j < 8; j++) {
                    colsum[j] += o[j];
                    colsq[j] = fmaf(o[j], o[j], colsq[j]);
                }
            }
        }

        // block reduction of per-channel sum / sumsq in dead As1 region:
        // red_s[32][128] then red_q[32][128]
        float* red_s = As1;
        float* red_q = As1 + 32 * 128;
#pragma unroll
        for (int j = 0; j < 8; j++) {
            red_s[ty * 128 + tx * 8 + j] = colsum[j];
            red_q[ty * 128 + tx * 8 + j] = colsq[j];
        }
        __syncthreads();
        if (tid < 128) {
            float s = 0.f, q = 0.f;
#pragma unroll
            for (int t = 0; t < 32; t++) {
                s += red_s[t * 128 + tid];
                q += red_q[t * 128 + tid];
            }
            if (which) {
                atomicAdd(&g_sum2[tid], s);
                atomicAdd(&g_sq2[tid], q);
            } else {
                atomicAdd(&g_sum1[tid], s);
                atomicAdd(&g_sq1[tid], q);
            }
        }
        // NOTE: next iteration starts with __syncthreads(), protecting red/As1 & Bs
    }
}

// ------------------------- K5: finalize BN stats -------------------------
__global__ void finalize_kernel() {
    int t = threadIdx.x;
    const float invN = 1.f / (float)NN;
    if (t < HIDC) {
        float mu = g_sum1[t] * invN;
        float var = fmaxf(g_sq1[t] * invN - mu * mu, 0.f);
        g_mu1[t] = mu;
        g_inv1[t] = rsqrtf(var + BN_EPS);
    } else {
        int c = t - HIDC;
        float mu = g_sum2[c] * invN;
        float var = fmaxf(g_sq2[c] * invN - mu * mu, 0.f);
        g_mu2[c] = mu;
        g_inv2[c] = rsqrtf(var + BN_EPS);
    }
}

// ------------------------- K6: BN+relu, node_pool out, graph max/sum pooling ----
__global__ void __launch_bounds__(256) combine_kernel(
    const int* __restrict__ batch,
    const float* __restrict__ bn1_b,
    const float* __restrict__ bn2_g, const float* __restrict__ bn2_b,
    const float* __restrict__ bn3_g, const float* __restrict__ bn3_b,
    float* __restrict__ out) {
    int c = threadIdx.x & 127;
    int half = threadIdx.x >> 7;
    float h0c = fmaxf(bn1_b[c], 0.f);
    float mu1 = g_mu1[c], iv1 = g_inv1[c], ga1 = bn2_g[c], be1 = bn2_b[c];
    float mu2 = g_mu2[c], iv2 = g_inv2[c], ga2 = bn3_g[c], be2 = bn3_b[c];

    int start = blockIdx.x * 256;
    int end = min(NN, start + 256);
    float mx1 = 0.f, sm1 = 0.f, mx2 = 0.f, sm2 = 0.f;
    int curg = -1;

    for (int n = start + half; n < end; n += 2) {
        int g = batch[n];
        if (g != curg) {
            if (curg >= 0) {
                atomicMax((int*)&g_gmax1[curg * HIDC + c], __float_as_int(mx1));
                atomicAdd(&g_gsum1[curg * HIDC + c], sm1);
                atomicMax((int*)&g_gmax2[curg * HIDC + c], __float_as_int(mx2));
                atomicAdd(&g_gsum2[curg * HIDC + c], sm2);
            }
            curg = g;
            mx1 = 0.f; sm1 = 0.f; mx2 = 0.f; sm2 = 0.f;
        }
        float r1 = g_R1[n * HIDC + c];
        float h1 = fmaxf(fmaf(ga1 * (r1 - mu1), iv1, be1), 0.f);
        float r2 = g_R2[n * HIDC + c];
        float h2 = fmaxf(fmaf(ga2 * (r2 - mu2), iv2, be2), 0.f);
        out[n * HIDC + c] = h0c + h1 + h2;
        mx1 = fmaxf(mx1, h1); sm1 += h1;
        mx2 = fmaxf(mx2, h2); sm2 += h2;
    }
    if (curg >= 0) {
        atomicMax((int*)&g_gmax1[curg * HIDC + c], __float_as_int(mx1));
        atomicAdd(&g_gsum1[curg * HIDC + c], sm1);
        atomicMax((int*)&g_gmax2[curg * HIDC + c], __float_as_int(mx2));
        atomicAdd(&g_gsum2[curg * HIDC + c], sm2);
    }
}

// ------------------------- K7: graph head -------------------------
__global__ void head_kernel(
    const float* __restrict__ bn1_b,
    const float* __restrict__ Wp0, const float* __restrict__ bp0,
    const float* __restrict__ Wp1, const float* __restrict__ bp1,
    const float* __restrict__ Wp2, const float* __restrict__ bp2,
    float* __restrict__ out) {
    int g = blockIdx.x, c = threadIdx.x;
    float invn = 1.f / fmaxf((float)g_gcnt[g], 1.f);
    float acc = bp0[c] + bp1[c] + bp2[c];
    const float* w0 = Wp0 + c * 256;
    const float* w1 = Wp1 + c * 256;
    const float* w2 = Wp2 + c * 256;
    for (int k = 0; k < HIDC; k++) {
        float h0k = fmaxf(bn1_b[k], 0.f);
        acc = fmaf(w0[k] + w0[128 + k], h0k, acc);
        acc = fmaf(w1[k], g_gmax1[g * HIDC + k], acc);
        acc = fmaf(w1[128 + k], g_gsum1[g * HIDC + k] * invn, acc);
        acc = fmaf(w2[k], g_gmax2[g * HIDC + k], acc);
        acc = fmaf(w2[128 + k], g_gsum2[g * HIDC + k] * invn, acc);
    }
    out[NN * HIDC + g * HIDC + c] = acc;
}

// ------------------------- launch -------------------------
extern "C" void kernel_launch(void* const* d_in, const int* in_sizes, int n_in,
                              void* d_out, int out_size) {
    const float* edge_attr = (const float*)d_in[1];
    const float* bn1_b = (const float*)d_in[5];
    const float* bn2_g = (const float*)d_in[6];
    const float* bn2_b = (const float*)d_in[7];
    const float* bn3_g = (const float*)d_in[8];
    const float* bn3_b = (const float*)d_in[9];
    const float* c1_W1 = (const float*)d_in[10];
    const float* c1_b1 = (const float*)d_in[11];
    const float* c1_W2 = (const float*)d_in[12];
    const float* c1_b2 = (const float*)d_in[13];
    const float* c2_W1 = (const float*)d_in[14];
    const float* c2_b1 = (const float*)d_in[15];
    const float* c2_W2 = (const float*)d_in[16];
    const float* c2_b2 = (const float*)d_in[17];
    const float* Wp0 = (const float*)d_in[18];
    const float* bp0 = (const float*)d_in[19];
    const float* Wp1 = (const float*)d_in[20];
    const float* bp1 = (const float*)d_in[21];
    const float* Wp2 = (const float*)d_in[22];
    const float* bp2 = (const float*)d_in[23];
    const int* edge_index = (const int*)d_in[24];
    const int* batch = (const int*)d_in[25];
    float* out = (float*)d_out;

    cudaFuncSetAttribute(fused_kernel, cudaFuncAttributeMaxDynamicSharedMemorySize,
                         FUSED_SMEM);

    zero_kernel<<<256, 256>>>();
    hist_kernel<<<2048, 256>>>(edge_index, batch);
    scanA_kernel<<<NBLK, 1024>>>();
    scanB_kernel<<<1, 128>>>();
    scanC_kernel<<<NBLK, 1024>>>();
    scatter_kernel<<<2048, 256>>>(edge_index, (const float2*)edge_attr);
    fused_kernel<<<(NN + 127) / 128, 512, FUSED_SMEM>>>(
        c1_W1, c1_b1, c1_W2, c1_b2, c2_W1, c2_b1, c2_W2, c2_b2);
    finalize_kernel<<<1, 256>>>();
    combine_kernel<<<(NN + 255) / 256, 256>>>(batch, bn1_b, bn2_g, bn2_b, bn3_g,
                                              bn3_b, out);
    head_kernel<<<GG, HIDC>>>(bn1_b, Wp0, bp0, Wp1, bp1, Wp2, bp2, out);
}